// round 13
// baseline (speedup 1.0000x reference)
#include <cuda_runtime.h>
#include <cstdint>
#include <cstddef>
#include <math.h>

#define TT 512
#define BB 32
#define NBLK 128   // persistent recurrence grid size

typedef unsigned long long ull;

// ---------------------------------------------------------------------------
// Packed f32x2 helpers (sm_100+: one FFMA2 = 2 fp32 FMAs)
// ---------------------------------------------------------------------------
__device__ __forceinline__ ull pk_pack(float lo, float hi)
{
    ull r; asm("mov.b64 %0, {%1, %2};" : "=l"(r) : "f"(lo), "f"(hi)); return r;
}
__device__ __forceinline__ void pk_unpack(ull v, float& lo, float& hi)
{
    asm("mov.b64 {%0, %1}, %2;" : "=f"(lo), "=f"(hi) : "l"(v));
}
__device__ __forceinline__ ull pk_ffma2(ull a, ull b, ull c)
{
    ull d; asm("fma.rn.f32x2 %0, %1, %2, %3;" : "=l"(d) : "l"(a), "l"(b), "l"(c));
    return d;
}

// ---------------------------------------------------------------------------
// Device-global scratch (no allocation allowed)
// ---------------------------------------------------------------------------
__device__ float g_Xg[134217728];        // 16384 x 8192 gates (+biases), [b][t][8192]
__device__ float g_Y0[33554432];         // layer-0 output, (T,B,2048)
__device__ float g_ht[2 * 2 * 1024 * 32];// h state, [buf][d][u][b] (double buffered)
__device__ float g_cst[2 * 1024 * 32];   // c state, [d][u][b]
__device__ int   g_len[BB];
__device__ int   g_nact[TT];

// software grid barrier state (zero-initialized at module load)
__device__ volatile unsigned g_gen;
__device__ unsigned          g_count;

__device__ __forceinline__ void grid_sync()
{
    __syncthreads();
    if (threadIdx.x == 0) {
        __threadfence();
        unsigned gen = g_gen;
        if (atomicAdd(&g_count, 1u) == NBLK - 1) {
            g_count = 0;
            __threadfence();
            g_gen = gen + 1;
        } else {
            while (g_gen == gen) { }
        }
    }
    __syncthreads();
}

// ---------------------------------------------------------------------------
// Length extraction from mask (mask[b,t] = t >= len[b]); dtype-robust.
// ---------------------------------------------------------------------------
__global__ void pk_lengths(const unsigned char* __restrict__ m8)
{
    __shared__ int slen[BB];
    int b = threadIdx.x;
    if (b < BB) {
        const int* m32 = (const int*)m8;
        int first1 = TT; bool ok = true;
        for (int t = 0; t < TT; ++t) {
            bool tv = (m8[b * TT + t] != 0);
            if (tv) { if (first1 == TT) first1 = t; }
            else if (first1 != TT) ok = false;   // non-monotone -> wrong dtype
        }
        unsigned bal = __ballot_sync(0xffffffffu, ok);
        if (bal != 0xffffffffu) {
            first1 = TT;
            for (int t = 0; t < TT; ++t) {
                if (m32[b * TT + t] != 0 && first1 == TT) first1 = t;
            }
        }
        slen[b] = first1;
        g_len[b] = first1;
    }
    __syncthreads();
    for (int s = threadIdx.x; s < TT; s += blockDim.x) {
        int c = 0;
        #pragma unroll
        for (int j = 0; j < BB; ++j) c += (slen[j] > s) ? 1 : 0;
        g_nact[s] = c;   // lens sorted descending -> active batches are prefix
    }
}

// ---------------------------------------------------------------------------
// Zero helpers
// ---------------------------------------------------------------------------
__global__ void pk_zero_y0()
{
    size_t n = 33554432ULL;
    size_t st = (size_t)gridDim.x * blockDim.x;
    for (size_t i = (size_t)blockIdx.x * blockDim.x + threadIdx.x; i < n; i += st)
        g_Y0[i] = 0.f;
}
__global__ void pk_zero_out(float* __restrict__ p, size_t n)
{
    size_t st = (size_t)gridDim.x * blockDim.x;
    for (size_t i = (size_t)blockIdx.x * blockDim.x + threadIdx.x; i < n; i += st)
        p[i] = 0.f;
}

// ---------------------------------------------------------------------------
// Input-projection GEMM (f32x2 packed math):
//   Xg[(b*512+t)*8192 + n] = sum_k A[t][b][k] * W[n][k] + b1[n] + b2[n]
// 128x128 tile, BK=8, 256 threads, 8x8 microtile as 8x4 f32x2 pairs.
// Fully-invalid tiles (t0 >= len[b]) are skipped.
// ---------------------------------------------------------------------------
__global__ __launch_bounds__(256)
void pk_gemm(const float* __restrict__ Xin, int use_y0,
             const float* __restrict__ W,
             const float* __restrict__ b1, const float* __restrict__ b2)
{
    int rowTile = blockIdx.y;
    int b  = rowTile >> 2;
    int t0 = (rowTile & 3) << 7;
    if (t0 >= g_len[b]) return;
    int n0 = blockIdx.x << 7;

    const float* A = use_y0 ? g_Y0 : Xin;

    __shared__ float As[8][132];
    __shared__ float Bs[8][132];

    int tid = threadIdx.x;
    int lr = tid >> 1, lk = (tid & 1) << 2;   // loader: row 0..127, k 0/4
    int tr = tid >> 4, tc = tid & 15;         // 16x16 compute grid

    const float* Aptr = A + (size_t)(t0 + lr) * 65536 + (size_t)b * 2048 + lk;
    const float* Wptr = W + (size_t)(n0 + lr) * 2048 + lk;

    float4 av = *(const float4*)(Aptr);
    float4 bv = *(const float4*)(Wptr);

    ull acc2[8][4];
    #pragma unroll
    for (int i = 0; i < 8; ++i)
        #pragma unroll
        for (int j = 0; j < 4; ++j) acc2[i][j] = 0ULL;   // {0.f, 0.f}

    for (int k0 = 0; k0 < 2048; k0 += 8) {
        __syncthreads();   // previous iteration's smem reads done
        As[lk + 0][lr] = av.x; As[lk + 1][lr] = av.y;
        As[lk + 2][lr] = av.z; As[lk + 3][lr] = av.w;
        Bs[lk + 0][lr] = bv.x; Bs[lk + 1][lr] = bv.y;
        Bs[lk + 2][lr] = bv.z; Bs[lk + 3][lr] = bv.w;
        __syncthreads();

        if (k0 + 8 < 2048) {   // stage next tile (overlaps compute)
            av = *(const float4*)(Aptr + k0 + 8);
            bv = *(const float4*)(Wptr + k0 + 8);
        }

        #pragma unroll
        for (int kk = 0; kk < 8; ++kk) {
            float4 a0 = *(float4*)&As[kk][tr * 4];
            float4 a1 = *(float4*)&As[kk][64 + tr * 4];
            ulonglong2 bp0 = *(ulonglong2*)&Bs[kk][tc * 4];       // cols n0+tc*4 +0..3
            ulonglong2 bp1 = *(ulonglong2*)&Bs[kk][64 + tc * 4];  // cols n0+64+tc*4 +0..3
            ull bp[4] = {bp0.x, bp0.y, bp1.x, bp1.y};
            float ar8[8] = {a0.x, a0.y, a0.z, a0.w, a1.x, a1.y, a1.z, a1.w};
            #pragma unroll
            for (int i = 0; i < 8; ++i) {
                ull ai = pk_pack(ar8[i], ar8[i]);
                #pragma unroll
                for (int j = 0; j < 4; ++j)
                    acc2[i][j] = pk_ffma2(ai, bp[j], acc2[i][j]);
            }
        }
    }

    float4 q1a = *(const float4*)(b1 + n0 + tc * 4);
    float4 q2a = *(const float4*)(b2 + n0 + tc * 4);
    float4 q1b = *(const float4*)(b1 + n0 + 64 + tc * 4);
    float4 q2b = *(const float4*)(b2 + n0 + 64 + tc * 4);
    float bs[8] = {q1a.x + q2a.x, q1a.y + q2a.y, q1a.z + q2a.z, q1a.w + q2a.w,
                   q1b.x + q2b.x, q1b.y + q2b.y, q1b.z + q2b.z, q1b.w + q2b.w};

    #pragma unroll
    for (int i = 0; i < 8; ++i) {
        int r = (i < 4) ? (tr * 4 + i) : (64 + tr * 4 + i - 4);
        size_t row = (size_t)b * 512 + t0 + r;
        float a8[8];
        pk_unpack(acc2[i][0], a8[0], a8[1]);
        pk_unpack(acc2[i][1], a8[2], a8[3]);
        pk_unpack(acc2[i][2], a8[4], a8[5]);
        pk_unpack(acc2[i][3], a8[6], a8[7]);
        float4 v0 = make_float4(a8[0] + bs[0], a8[1] + bs[1],
                                a8[2] + bs[2], a8[3] + bs[3]);
        float4 v1 = make_float4(a8[4] + bs[4], a8[5] + bs[5],
                                a8[6] + bs[6], a8[7] + bs[7]);
        *(float4*)(g_Xg + row * 8192 + n0 + tc * 4)      = v0;
        *(float4*)(g_Xg + row * 8192 + n0 + 64 + tc * 4) = v1;
    }
}

// ---------------------------------------------------------------------------
// Persistent recurrence kernel (f32x2 packed math):
// Block = (dir d, 16 units) -> 64 gate columns x 32 batches.
// Thread = 1 col x 8 batches (4 packed pairs); chunk loads software-pipelined.
// ---------------------------------------------------------------------------
__global__ __launch_bounds__(256, 1)
void pk_recur(const float* __restrict__ Whh_l,
              float* __restrict__ outp, int use_out,
              float* __restrict__ out_final, int lidx0)
{
    __shared__ float Hs[32][32];      // h chunk [k][b]
    __shared__ float Ws[64][33];      // W chunk [col][k], padded (conflict-free)
    __shared__ float Sg[32][68];      // gates  [b][col], padded
    __shared__ int   slen[32];

    int tid = threadIdx.x;
    int d  = blockIdx.x >> 6;
    int u0 = (blockIdx.x & 63) << 4;

    if (tid < 32) slen[tid] = g_len[tid];
    __syncthreads();

    // zero this block's h (both buffers) and c slices
    for (int r = tid; r < 512; r += 256) {
        int uu = r >> 5, b = r & 31;
        int ci = d * 32768 + (u0 + uu) * 32 + b;
        g_ht[ci] = 0.f; g_ht[65536 + ci] = 0.f; g_cst[ci] = 0.f;
    }
    grid_sync();

    // compute mapping: thread = col (tid&63) x 8 batches (bg = tid>>6)
    int col = tid & 63;
    int bg  = tid >> 6;            // warp-uniform
    int b0  = bg << 3;
    int gate = col >> 4, uu = col & 15;
    int gcol = d * 4096 + gate * 1024 + u0 + uu;   // Xg column == Whh row

    // loader mapping
    int kk_l = tid >> 3, b4 = (tid & 7) << 2;       // Hs: [kk_l][b4..b4+3]
    int row0 = tid >> 3, row1 = 32 + (tid >> 3);    // Ws rows
    int k4   = (tid & 7) << 2;
    int wr0  = d * 4096 + (row0 >> 4) * 1024 + u0 + (row0 & 15);
    int wr1  = d * 4096 + (row1 >> 4) * 1024 + u0 + (row1 & 15);
    const float* wp0 = Whh_l + (size_t)wr0 * 1024 + k4;
    const float* wp1 = Whh_l + (size_t)wr1 * 1024 + k4;

    for (int s = 0; s < TT; ++s) {
        int nact = g_nact[s];

        // Xg gather (issues early; overlaps chunk-0 staging)
        float xv[8];
        #pragma unroll
        for (int j = 0; j < 8; ++j) {
            int b = b0 + j;
            float v = 0.f;
            if (b < nact) {
                int t = d ? (slen[b] - 1 - s) : s;
                v = g_Xg[(size_t)(b * 512 + t) * 8192 + gcol];
            }
            xv[j] = v;
        }
        ull acc2[4];
        #pragma unroll
        for (int j = 0; j < 4; ++j) acc2[j] = pk_pack(xv[2 * j], xv[2 * j + 1]);

        const float* hbuf = g_ht + (size_t)(s & 1) * 65536 + d * 32768;

        // stage chunk 0
        float4 hv  = *(const float4*)(hbuf + (size_t)kk_l * 32 + b4);
        float4 wv0 = *(const float4*)(wp0);
        float4 wv1 = *(const float4*)(wp1);

        for (int k0 = 0; k0 < 1024; k0 += 32) {
            __syncthreads();   // previous chunk's smem reads done
            *(float4*)&Hs[kk_l][b4] = hv;
            Ws[row0][k4 + 0] = wv0.x; Ws[row0][k4 + 1] = wv0.y;
            Ws[row0][k4 + 2] = wv0.z; Ws[row0][k4 + 3] = wv0.w;
            Ws[row1][k4 + 0] = wv1.x; Ws[row1][k4 + 1] = wv1.y;
            Ws[row1][k4 + 2] = wv1.z; Ws[row1][k4 + 3] = wv1.w;
            __syncthreads();

            int k0n = k0 + 32;
            if (k0n < 1024) {   // stage next chunk (overlaps compute)
                hv  = *(const float4*)(hbuf + (size_t)(k0n + kk_l) * 32 + b4);
                wv0 = *(const float4*)(wp0 + k0n);
                wv1 = *(const float4*)(wp1 + k0n);
            }

            if (b0 < nact) {
                #pragma unroll
                for (int kk = 0; kk < 32; ++kk) {
                    float w = Ws[col][kk];
                    ull ww = pk_pack(w, w);
                    ulonglong2 hA = *(ulonglong2*)&Hs[kk][b0];      // {h0,h1},{h2,h3}
                    ulonglong2 hB = *(ulonglong2*)&Hs[kk][b0 + 4];  // {h4,h5},{h6,h7}
                    acc2[0] = pk_ffma2(ww, hA.x, acc2[0]);
                    acc2[1] = pk_ffma2(ww, hA.y, acc2[1]);
                    acc2[2] = pk_ffma2(ww, hB.x, acc2[2]);
                    acc2[3] = pk_ffma2(ww, hB.y, acc2[3]);
                }
            }
        }
        __syncthreads();

        #pragma unroll
        for (int j = 0; j < 4; ++j) {
            float lo, hi;
            pk_unpack(acc2[j], lo, hi);
            Sg[b0 + 2 * j][col]     = lo;
            Sg[b0 + 2 * j + 1][col] = hi;
        }
        __syncthreads();

        float* hw   = g_ht + (size_t)((s + 1) & 1) * 65536 + d * 32768;
        float* cbuf = g_cst + d * 32768;

        #pragma unroll
        for (int r = 0; r < 2; ++r) {
            int cid = tid + (r << 8);          // 512 cells = 16 units x 32 batches
            int cu = cid & 15, cb = cid >> 4;
            if (cb < nact) {
                float gi = Sg[cb][cu];
                float gf = Sg[cb][16 + cu];
                float gg = Sg[cb][32 + cu];
                float go = Sg[cb][48 + cu];
                float iv = 1.f / (1.f + expf(-gi));
                float fv = 1.f / (1.f + expf(-gf));
                float gv = tanhf(gg);
                float ov = 1.f / (1.f + expf(-go));
                int ci = (u0 + cu) * 32 + cb;
                float cn = fv * cbuf[ci] + iv * gv;
                float hn = ov * tanhf(cn);
                cbuf[ci] = cn;
                hw[ci]   = hn;
                float* yout = use_out ? outp : g_Y0;
                int t = d ? (slen[cb] - 1 - s) : s;
                yout[(size_t)t * 65536 + (size_t)cb * 2048 + d * 1024 + u0 + cu] = hn;
            }
        }
        grid_sync();
    }

    // epilogue: save final h/c. Final h for batch b is in buffer (len[b] & 1).
    for (int r = tid; r < 512; r += 256) {
        int uu2 = r >> 5, b = r & 31;
        int buf = slen[b] & 1;
        int ci  = d * 32768 + (u0 + uu2) * 32 + b;
        float hv2 = g_ht[(size_t)buf * 65536 + ci];
        float cv2 = g_cst[ci];
        size_t o = (size_t)(lidx0 + d) * 32768 + (size_t)b * 1024 + (u0 + uu2);
        out_final[33554432ULL + o]          = hv2;
        out_final[33554432ULL + 131072 + o] = cv2;
    }
}

// ---------------------------------------------------------------------------
// Launch: 7 graph nodes total
// ---------------------------------------------------------------------------
extern "C" void kernel_launch(void* const* d_in, const int* in_sizes, int n_in,
                              void* d_out, int out_size)
{
    const float* x            = (const float*)d_in[0];
    const unsigned char* mask = (const unsigned char*)d_in[1];
    const float* Wih          = (const float*)d_in[2];
    const float* Whh          = (const float*)d_in[3];
    const float* bih          = (const float*)d_in[4];
    const float* bhh          = (const float*)d_in[5];
    float* out = (float*)d_out;

    pk_lengths<<<1, 256>>>(mask);
    pk_zero_y0<<<2048, 256>>>();
    pk_zero_out<<<2048, 256>>>(out, (size_t)33554432ULL);

    for (int l = 0; l < 2; ++l) {
        pk_gemm<<<dim3(64, 128), 256>>>(
            x, l,
            Wih + (size_t)l * 2 * 4096 * 2048,
            bih + (size_t)l * 8192,
            bhh + (size_t)l * 8192);
        const float* whl = Whh + (size_t)l * 2 * 4096 * 1024;
        pk_recur<<<NBLK, 256>>>(whl, out, l, out, l * 2);
    }
}

// round 17
// speedup vs baseline: 1.2961x; 1.2961x over previous
#include <cuda_runtime.h>
#include <cuda_bf16.h>
#include <cstdint>
#include <cstddef>
#include <math.h>

#define TT 512
#define BB 32
#define NBLK 128   // persistent recurrence grid size

typedef unsigned long long ull;

// ---------------------------------------------------------------------------
// Device-global scratch (no allocation allowed)
// ---------------------------------------------------------------------------
__device__ float g_Xg[134217728];        // 16384 x 8192 gates (+biases), [b][t][8192]
__device__ float g_Y0[33554432];         // layer-0 output, (T,B,2048)
__device__ __nv_bfloat16 g_Ah[33554432]; // A split hi: 16384 x 2048, rows (b*512+t)
__device__ __nv_bfloat16 g_Al[33554432]; // A split lo
__device__ __nv_bfloat16 g_Wh[16777216]; // W split hi: 8192 x 2048
__device__ __nv_bfloat16 g_Wl[16777216]; // W split lo
__device__ float g_ht[2 * 2 * 1024 * 32];// h state, [buf][d][u][b] (double buffered)
__device__ float g_cst[2 * 1024 * 32];   // c state, [d][u][b]
__device__ int   g_len[BB];
__device__ int   g_nact[TT];

// software grid barrier state (zero-initialized at module load)
__device__ volatile unsigned g_gen;
__device__ unsigned          g_count;

__device__ __forceinline__ void grid_sync()
{
    __syncthreads();
    if (threadIdx.x == 0) {
        __threadfence();
        unsigned gen = g_gen;
        if (atomicAdd(&g_count, 1u) == NBLK - 1) {
            g_count = 0;
            __threadfence();
            g_gen = gen + 1;
        } else {
            while (g_gen == gen) { }
        }
    }
    __syncthreads();
}

// ---------------------------------------------------------------------------
// sm_80-era async-copy / ldmatrix / mma helpers (all legal on plain sm_103)
// ---------------------------------------------------------------------------
__device__ __forceinline__ uint32_t su32(const void* p)
{
    uint32_t a;
    asm("{ .reg .u64 t; cvta.to.shared.u64 t, %1; cvt.u32.u64 %0, t; }"
        : "=r"(a) : "l"(p));
    return a;
}
__device__ __forceinline__ void cp16(uint32_t dst, const void* src)
{
    asm volatile("cp.async.ca.shared.global [%0], [%1], 16;" :: "r"(dst), "l"(src));
}
__device__ __forceinline__ void cp_commit()
{
    asm volatile("cp.async.commit_group;" ::: "memory");
}
__device__ __forceinline__ void cp_wait1()
{
    asm volatile("cp.async.wait_group 1;" ::: "memory");
}
__device__ __forceinline__ void cp_wait0()
{
    asm volatile("cp.async.wait_group 0;" ::: "memory");
}
__device__ __forceinline__ void ldm4(uint32_t* r, uint32_t a)
{
    asm volatile("ldmatrix.sync.aligned.m8n8.x4.shared.b16 {%0,%1,%2,%3}, [%4];"
                 : "=r"(r[0]), "=r"(r[1]), "=r"(r[2]), "=r"(r[3]) : "r"(a));
}
__device__ __forceinline__ void ldm2(uint32_t* r, uint32_t a)
{
    asm volatile("ldmatrix.sync.aligned.m8n8.x2.shared.b16 {%0,%1}, [%2];"
                 : "=r"(r[0]), "=r"(r[1]) : "r"(a));
}
__device__ __forceinline__ void mma16816(float* c, const uint32_t* a, const uint32_t* b)
{
    asm volatile(
        "mma.sync.aligned.m16n8k16.row.col.f32.bf16.bf16.f32 "
        "{%0,%1,%2,%3}, {%4,%5,%6,%7}, {%8,%9}, {%0,%1,%2,%3};"
        : "+f"(c[0]), "+f"(c[1]), "+f"(c[2]), "+f"(c[3])
        : "r"(a[0]), "r"(a[1]), "r"(a[2]), "r"(a[3]), "r"(b[0]), "r"(b[1]));
}

// ---------------------------------------------------------------------------
// Length extraction from mask (mask[b,t] = t >= len[b]); dtype-robust.
// ---------------------------------------------------------------------------
__global__ void pk_lengths(const unsigned char* __restrict__ m8)
{
    __shared__ int slen[BB];
    int b = threadIdx.x;
    if (b < BB) {
        const int* m32 = (const int*)m8;
        int first1 = TT; bool ok = true;
        for (int t = 0; t < TT; ++t) {
            bool tv = (m8[b * TT + t] != 0);
            if (tv) { if (first1 == TT) first1 = t; }
            else if (first1 != TT) ok = false;   // non-monotone -> wrong dtype
        }
        unsigned bal = __ballot_sync(0xffffffffu, ok);
        if (bal != 0xffffffffu) {
            first1 = TT;
            for (int t = 0; t < TT; ++t) {
                if (m32[b * TT + t] != 0 && first1 == TT) first1 = t;
            }
        }
        slen[b] = first1;
        g_len[b] = first1;
    }
    __syncthreads();
    for (int s = threadIdx.x; s < TT; s += blockDim.x) {
        int c = 0;
        #pragma unroll
        for (int j = 0; j < BB; ++j) c += (slen[j] > s) ? 1 : 0;
        g_nact[s] = c;   // lens sorted descending -> active batches are prefix
    }
}

// ---------------------------------------------------------------------------
// Zero helpers
// ---------------------------------------------------------------------------
__global__ void pk_zero_y0()
{
    size_t n = 33554432ULL;
    size_t st = (size_t)gridDim.x * blockDim.x;
    for (size_t i = (size_t)blockIdx.x * blockDim.x + threadIdx.x; i < n; i += st)
        g_Y0[i] = 0.f;
}
__global__ void pk_zero_out(float* __restrict__ p, size_t n)
{
    size_t st = (size_t)gridDim.x * blockDim.x;
    for (size_t i = (size_t)blockIdx.x * blockDim.x + threadIdx.x; i < n; i += st)
        p[i] = 0.f;
}

// ---------------------------------------------------------------------------
// bf16 hi/lo split kernels.
// ---------------------------------------------------------------------------
__global__ void pk_split_a(const float* __restrict__ x, int use_y0)
{
    const float* src = use_y0 ? g_Y0 : x;
    size_t n = 33554432ULL;
    size_t st = (size_t)gridDim.x * blockDim.x;
    for (size_t i = (size_t)blockIdx.x * blockDim.x + threadIdx.x; i < n; i += st) {
        int r = (int)(i >> 11), k = (int)(i & 2047);
        int b = r >> 9, t = r & 511;
        float v = src[(size_t)t * 65536 + b * 2048 + k];
        __nv_bfloat16 hi = __float2bfloat16(v);
        g_Ah[i] = hi;
        g_Al[i] = __float2bfloat16(v - __bfloat162float(hi));
    }
}
__global__ void pk_split_w(const float* __restrict__ W)
{
    size_t n = 16777216ULL;
    size_t st = (size_t)gridDim.x * blockDim.x;
    for (size_t i = (size_t)blockIdx.x * blockDim.x + threadIdx.x; i < n; i += st) {
        float v = W[i];
        __nv_bfloat16 hi = __float2bfloat16(v);
        g_Wh[i] = hi;
        g_Wl[i] = __float2bfloat16(v - __bfloat162float(hi));
    }
}

// ---------------------------------------------------------------------------
// Tensor-core (mma.sync bf16-split) input-projection GEMM.
//   Xg[(b*512+t)*8192 + n] = sum_k A[r][k]*W[n][k] + b1[n] + b2[n]
// 128x128 tile, BK=32, 8 warps (2x4), warp tile 64x32 = 4x4 m16n8k16 atoms,
// 3 MMAs per atom per k16 (hh + hl + lh) into fp32 accumulators.
// cp.async double-buffered stages; smem rows stride 40 bf16.
// FIX vs R15: global loader pointers now include the per-thread k offset
// (lkc0), matching the smem destination slots.
// ---------------------------------------------------------------------------
#define SSTG 40960                      // bytes per stage (4 arrays x 128x40 bf16)
#define SOFF_AL 10240
#define SOFF_BH 20480
#define SOFF_BL 30720
#define GEMM_SMEM (2 * SSTG)

__global__ __launch_bounds__(256, 1)
void pk_gemm_mma(const float* __restrict__ b1, const float* __restrict__ b2)
{
    int mt = blockIdx.y;
    int b  = mt >> 2;
    int t0 = (mt & 3) << 7;
    if (t0 >= g_len[b]) return;
    int n0 = blockIdx.x << 7;

    extern __shared__ char smem[];
    uint32_t sb = su32(smem);

    int tid  = threadIdx.x;
    int wid  = tid >> 5, lane = tid & 31;
    int wm   = wid >> 2, wn = wid & 3;          // warp grid 2(M) x 4(N)

    int rowBase = b * 512 + t0;

    // loader mapping: 2 chunks of 16B per array per thread
    int cid0 = tid * 2;
    int lrow0 = cid0 >> 2,  lkc0 = (cid0 & 3) * 8;   // lkc0 in {0, 16}
    // FIX: global pointers include the thread's k offset lkc0
    const __nv_bfloat16* pAh = g_Ah + (size_t)(rowBase + lrow0) * 2048 + lkc0;
    const __nv_bfloat16* pAl = g_Al + (size_t)(rowBase + lrow0) * 2048 + lkc0;
    const __nv_bfloat16* pBh = g_Wh + (size_t)(n0 + lrow0) * 2048 + lkc0;
    const __nv_bfloat16* pBl = g_Wl + (size_t)(n0 + lrow0) * 2048 + lkc0;
    uint32_t so0 = (uint32_t)(lrow0 * 40 + lkc0) * 2;
    uint32_t so1 = (uint32_t)(lrow0 * 40 + lkc0 + 8) * 2;

    float acc[16][4];
    #pragma unroll
    for (int i = 0; i < 16; ++i)
        #pragma unroll
        for (int j = 0; j < 4; ++j) acc[i][j] = 0.f;

    // ldmatrix addresses (per-lane, stage-relative)
    uint32_t aoff = (uint32_t)((wm * 64 + (lane & 15)) * 40 + (lane >> 4) * 8) * 2;
    uint32_t boff = (uint32_t)((wn * 32 + (lane & 7)) * 40 + ((lane >> 3) & 1) * 8) * 2;

    // prologue: stage 0
    {
        uint32_t d = sb;
        cp16(d + so0,            pAh);           cp16(d + so1,            pAh + 8);
        cp16(d + SOFF_AL + so0,  pAl);           cp16(d + SOFF_AL + so1,  pAl + 8);
        cp16(d + SOFF_BH + so0,  pBh);           cp16(d + SOFF_BH + so1,  pBh + 8);
        cp16(d + SOFF_BL + so0,  pBl);           cp16(d + SOFF_BL + so1,  pBl + 8);
        cp_commit();
    }

    for (int c = 0; c < 64; ++c) {
        if (c < 63) {
            int k0 = (c + 1) * 32;
            uint32_t d = sb + ((c + 1) & 1) * SSTG;
            cp16(d + so0,           pAh + k0);   cp16(d + so1,           pAh + k0 + 8);
            cp16(d + SOFF_AL + so0, pAl + k0);   cp16(d + SOFF_AL + so1, pAl + k0 + 8);
            cp16(d + SOFF_BH + so0, pBh + k0);   cp16(d + SOFF_BH + so1, pBh + k0 + 8);
            cp16(d + SOFF_BL + so0, pBl + k0);   cp16(d + SOFF_BL + so1, pBl + k0 + 8);
            cp_commit();
            cp_wait1();
        } else {
            cp_wait0();
        }
        __syncthreads();

        uint32_t base = sb + (c & 1) * SSTG;
        #pragma unroll
        for (int ks = 0; ks < 2; ++ks) {
            uint32_t kb = ks * 32;   // 16 bf16 = 32 bytes
            uint32_t ah[4][4], al[4][4], bh[4][2], bl[4][2];
            #pragma unroll
            for (int am = 0; am < 4; ++am) {
                uint32_t a = base + aoff + am * (16 * 80) + kb;
                ldm4(ah[am], a);
                ldm4(al[am], a + SOFF_AL);
            }
            #pragma unroll
            for (int an = 0; an < 4; ++an) {
                uint32_t a = base + SOFF_BH + boff + an * (8 * 80) + kb;
                ldm2(bh[an], a);
                ldm2(bl[an], a + (SOFF_BL - SOFF_BH));
            }
            #pragma unroll
            for (int am = 0; am < 4; ++am)
                #pragma unroll
                for (int an = 0; an < 4; ++an) {
                    float* cc = acc[am * 4 + an];
                    mma16816(cc, ah[am], bh[an]);
                    mma16816(cc, ah[am], bl[an]);
                    mma16816(cc, al[am], bh[an]);
                }
        }
        __syncthreads();
    }

    // epilogue: fragment-direct stores + fused biases
    #pragma unroll
    for (int an = 0; an < 4; ++an) {
        int col = n0 + wn * 32 + an * 8 + (lane & 3) * 2;
        float2 q1 = *(const float2*)(b1 + col);
        float2 q2 = *(const float2*)(b2 + col);
        float bx = q1.x + q2.x, by = q1.y + q2.y;
        #pragma unroll
        for (int am = 0; am < 4; ++am) {
            float* cc = acc[am * 4 + an];
            int r0 = rowBase + wm * 64 + am * 16 + (lane >> 2);
            float2 v0 = make_float2(cc[0] + bx, cc[1] + by);
            float2 v1 = make_float2(cc[2] + bx, cc[3] + by);
            *(float2*)(g_Xg + (size_t)r0 * 8192 + col)       = v0;
            *(float2*)(g_Xg + (size_t)(r0 + 8) * 8192 + col) = v1;
        }
    }
}

// ---------------------------------------------------------------------------
// Persistent recurrence kernel (R10 proven version):
// Block = (dir d, 16 units) -> 64 gate columns x 32 batches.
// Thread = 2 cols (cp, cp+32) x 4 batches; chunk loads software-pipelined.
// ---------------------------------------------------------------------------
__global__ __launch_bounds__(256, 1)
void pk_recur(const float* __restrict__ Whh_l,
              float* __restrict__ outp, int use_out,
              float* __restrict__ out_final, int lidx0)
{
    __shared__ float Hs[32][32];      // h chunk [k][b]
    __shared__ float Ws[64][33];      // W chunk [col][k], padded (conflict-free)
    __shared__ float Sg[32][68];      // gates  [b][col], padded
    __shared__ int   slen[32];

    int tid = threadIdx.x;
    int d  = blockIdx.x >> 6;
    int u0 = (blockIdx.x & 63) << 4;

    if (tid < 32) slen[tid] = g_len[tid];
    __syncthreads();

    // zero this block's h (both buffers) and c slices
    for (int r = tid; r < 512; r += 256) {
        int uu = r >> 5, b = r & 31;
        int ci = d * 32768 + (u0 + uu) * 32 + b;
        g_ht[ci] = 0.f; g_ht[65536 + ci] = 0.f; g_cst[ci] = 0.f;
    }
    grid_sync();

    // compute mapping: thread = (cp, bg): cols cp & cp+32, batches bg*4..+3
    int cp = tid & 31;
    int bg = tid >> 5;          // warp-uniform
    int b0 = bg << 2;
    int g0 = cp >> 4,        uu0 = cp & 15;
    int g1 = (cp + 32) >> 4, uu1 = (cp + 32) & 15;
    int gcol0 = d * 4096 + g0 * 1024 + u0 + uu0;
    int gcol1 = d * 4096 + g1 * 1024 + u0 + uu1;

    // loader mapping
    int kk_l = tid >> 3, b4 = (tid & 7) << 2;
    int row0 = tid >> 3, row1 = 32 + (tid >> 3);
    int k4   = (tid & 7) << 2;
    int wr0  = d * 4096 + (row0 >> 4) * 1024 + u0 + (row0 & 15);
    int wr1  = d * 4096 + (row1 >> 4) * 1024 + u0 + (row1 & 15);
    const float* wp0 = Whh_l + (size_t)wr0 * 1024 + k4;
    const float* wp1 = Whh_l + (size_t)wr1 * 1024 + k4;

    for (int s = 0; s < TT; ++s) {
        int nact = g_nact[s];

        float acc0[4], acc1[4];
        #pragma unroll
        for (int j = 0; j < 4; ++j) {
            int b = b0 + j;
            float v0 = 0.f, v1 = 0.f;
            if (b < nact) {
                int t = d ? (slen[b] - 1 - s) : s;
                size_t rbase = (size_t)(b * 512 + t) * 8192;
                v0 = g_Xg[rbase + gcol0];
                v1 = g_Xg[rbase + gcol1];
            }
            acc0[j] = v0; acc1[j] = v1;
        }

        const float* hbuf = g_ht + (size_t)(s & 1) * 65536 + d * 32768;

        float4 hv  = *(const float4*)(hbuf + (size_t)kk_l * 32 + b4);
        float4 wv0 = *(const float4*)(wp0);
        float4 wv1 = *(const float4*)(wp1);

        for (int k0 = 0; k0 < 1024; k0 += 32) {
            __syncthreads();
            *(float4*)&Hs[kk_l][b4] = hv;
            Ws[row0][k4 + 0] = wv0.x; Ws[row0][k4 + 1] = wv0.y;
            Ws[row0][k4 + 2] = wv0.z; Ws[row0][k4 + 3] = wv0.w;
            Ws[row1][k4 + 0] = wv1.x; Ws[row1][k4 + 1] = wv1.y;
            Ws[row1][k4 + 2] = wv1.z; Ws[row1][k4 + 3] = wv1.w;
            __syncthreads();

            int k0n = k0 + 32;
            if (k0n < 1024) {
                hv  = *(const float4*)(hbuf + (size_t)(k0n + kk_l) * 32 + b4);
                wv0 = *(const float4*)(wp0 + k0n);
                wv1 = *(const float4*)(wp1 + k0n);
            }

            if (b0 < nact) {
                #pragma unroll
                for (int kk = 0; kk < 32; ++kk) {
                    float w0 = Ws[cp][kk];
                    float w1 = Ws[cp + 32][kk];
                    float4 h = *(float4*)&Hs[kk][b0];
                    acc0[0] += w0 * h.x; acc0[1] += w0 * h.y;
                    acc0[2] += w0 * h.z; acc0[3] += w0 * h.w;
                    acc1[0] += w1 * h.x; acc1[1] += w1 * h.y;
                    acc1[2] += w1 * h.z; acc1[3] += w1 * h.w;
                }
            }
        }
        __syncthreads();

        #pragma unroll
        for (int j = 0; j < 4; ++j) {
            Sg[b0 + j][cp]      = acc0[j];
            Sg[b0 + j][cp + 32] = acc1[j];
        }
        __syncthreads();

        float* hw   = g_ht + (size_t)((s + 1) & 1) * 65536 + d * 32768;
        float* cbuf = g_cst + d * 32768;

        #pragma unroll
        for (int r = 0; r < 2; ++r) {
            int cid = tid + (r << 8);
            int cu = cid & 15, cb = cid >> 4;
            if (cb < nact) {
                float gi = Sg[cb][cu];
                float gf = Sg[cb][16 + cu];
                float gg = Sg[cb][32 + cu];
                float go = Sg[cb][48 + cu];
                float iv = 1.f / (1.f + expf(-gi));
                float fv = 1.f / (1.f + expf(-gf));
                float gv = tanhf(gg);
                float ov = 1.f / (1.f + expf(-go));
                int ci = (u0 + cu) * 32 + cb;
                float cn = fv * cbuf[ci] + iv * gv;
                float hn = ov * tanhf(cn);
                cbuf[ci] = cn;
                hw[ci]   = hn;
                float* yout = use_out ? outp : g_Y0;
                int t = d ? (slen[cb] - 1 - s) : s;
                yout[(size_t)t * 65536 + (size_t)cb * 2048 + d * 1024 + u0 + cu] = hn;
            }
        }
        grid_sync();
    }

    // epilogue: save final h/c. Final h for batch b is in buffer (len[b] & 1).
    for (int r = tid; r < 512; r += 256) {
        int uu2 = r >> 5, b = r & 31;
        int buf = slen[b] & 1;
        int ci  = d * 32768 + (u0 + uu2) * 32 + b;
        float hv2 = g_ht[(size_t)buf * 65536 + ci];
        float cv2 = g_cst[ci];
        size_t o = (size_t)(lidx0 + d) * 32768 + (size_t)b * 1024 + (u0 + uu2);
        out_final[33554432ULL + o]          = hv2;
        out_final[33554432ULL + 131072 + o] = cv2;
    }
}

// ---------------------------------------------------------------------------
// Launch: 11 graph nodes total
// ---------------------------------------------------------------------------
extern "C" void kernel_launch(void* const* d_in, const int* in_sizes, int n_in,
                              void* d_out, int out_size)
{
    const float* x            = (const float*)d_in[0];
    const unsigned char* mask = (const unsigned char*)d_in[1];
    const float* Wih          = (const float*)d_in[2];
    const float* Whh          = (const float*)d_in[3];
    const float* bih          = (const float*)d_in[4];
    const float* bhh          = (const float*)d_in[5];
    float* out = (float*)d_out;

    cudaFuncSetAttribute(pk_gemm_mma,
                         cudaFuncAttributeMaxDynamicSharedMemorySize, GEMM_SMEM);

    pk_lengths<<<1, 256>>>(mask);
    pk_zero_y0<<<2048, 256>>>();
    pk_zero_out<<<2048, 256>>>(out, (size_t)33554432ULL);

    for (int l = 0; l < 2; ++l) {
        pk_split_a<<<4096, 256>>>(x, l);
        pk_split_w<<<2048, 256>>>(Wih + (size_t)l * 16777216ULL);
        pk_gemm_mma<<<dim3(64, 128), 256, GEMM_SMEM>>>(
            bih + (size_t)l * 8192, bhh + (size_t)l * 8192);
        pk_recur<<<NBLK, 256>>>(Whh + (size_t)l * 8388608ULL, out, l, out, l * 2);
    }
}